// round 13
// baseline (speedup 1.0000x reference)
#include <cuda_runtime.h>
#include <cuda_bf16.h>
#include <math.h>
#include <stdint.h>

#define SEQ 2048
#define DM 1024
#define NH 16
#define DK 64

// fp32 intermediate (b_rotate projection)
__device__ float g_BR[SEQ * DM];

// split-bf16 proj inputs [4][SEQ][DM] (q,k,v,b_emb), weights transposed [4][n][k]
__device__ __nv_bfloat16 g_Xhi[4 * SEQ * DM];
__device__ __nv_bfloat16 g_Xlo[4 * SEQ * DM];
__device__ __nv_bfloat16 g_Whi[4 * DM * DM];
__device__ __nv_bfloat16 g_Wlo[4 * DM * DM];
// attention operands (written by proj epilogue, rope fused)
__device__ __nv_bfloat16 g_Qhi[SEQ * DM];
__device__ __nv_bfloat16 g_Qlo[SEQ * DM];
__device__ __nv_bfloat16 g_Khi[SEQ * DM];
__device__ __nv_bfloat16 g_Klo[SEQ * DM];
__device__ __nv_bfloat16 g_Vhi[SEQ * DM];
__device__ __nv_bfloat16 g_Vlo[SEQ * DM];

__device__ __forceinline__ uint32_t smem_u32(const void* p) {
    uint32_t a;
    asm("{ .reg .u64 t; cvta.to.shared.u64 t, %1; cvt.u32.u64 %0, t; }"
        : "=r"(a) : "l"(p));
    return a;
}
__device__ __forceinline__ void ldm_x4(uint32_t r[4], uint32_t addr) {
    asm volatile("ldmatrix.sync.aligned.m8n8.x4.shared.b16 {%0,%1,%2,%3}, [%4];"
                 : "=r"(r[0]), "=r"(r[1]), "=r"(r[2]), "=r"(r[3]) : "r"(addr));
}
__device__ __forceinline__ void ldm_x4t(uint32_t r[4], uint32_t addr) {
    asm volatile("ldmatrix.sync.aligned.m8n8.x4.trans.shared.b16 {%0,%1,%2,%3}, [%4];"
                 : "=r"(r[0]), "=r"(r[1]), "=r"(r[2]), "=r"(r[3]) : "r"(addr));
}
__device__ __forceinline__ void mma_bf16(float c[4], const uint32_t a[4],
                                         const uint32_t* b) {
    asm volatile(
        "mma.sync.aligned.m16n8k16.row.col.f32.bf16.bf16.f32 "
        "{%0,%1,%2,%3}, {%4,%5,%6,%7}, {%8,%9}, {%0,%1,%2,%3};"
        : "+f"(c[0]), "+f"(c[1]), "+f"(c[2]), "+f"(c[3])
        : "r"(a[0]), "r"(a[1]), "r"(a[2]), "r"(a[3]), "r"(b[0]), "r"(b[1]));
}
__device__ __forceinline__ uint32_t pack_bf16(float a, float b) {
    __nv_bfloat162 t = __floats2bfloat162_rn(a, b);
    return *(uint32_t*)&t;
}
__device__ __forceinline__ float bf2sum(uint32_t p) {
    __nv_bfloat162 b = *(__nv_bfloat162*)&p;
    return __bfloat162float(b.x) + __bfloat162float(b.y);
}
#define CP16(s, g) \
    asm volatile("cp.async.cg.shared.global [%0], [%1], 16;" \
                 :: "r"(s), "l"(g) : "memory")
#define CP_COMMIT() asm volatile("cp.async.commit_group;" ::: "memory")
#define CP_WAIT1()  asm volatile("cp.async.wait_group 1;" ::: "memory")
#define CP_WAIT0()  asm volatile("cp.async.wait_group 0;" ::: "memory")

// ---------------------------------------------------------------------------
// conv_x: fp32 inputs -> hi/lo bf16 [4][SEQ][DM]
// ---------------------------------------------------------------------------
__global__ __launch_bounds__(256) void conv_x(
    const float* __restrict__ q, const float* __restrict__ k,
    const float* __restrict__ v, const float* __restrict__ b)
{
    const int PER = SEQ * DM / 4;
    int t = blockIdx.x * 256 + threadIdx.x;
    int z = t / PER, i = t - z * PER;
    const float* src = (z == 0) ? q : (z == 1) ? k : (z == 2) ? v : b;
    float4 x = ((const float4*)src)[i];

    __nv_bfloat16 h0 = __float2bfloat16(x.x), h1 = __float2bfloat16(x.y);
    __nv_bfloat16 h2 = __float2bfloat16(x.z), h3 = __float2bfloat16(x.w);
    __nv_bfloat162 hA = {h0, h1}, hB = {h2, h3};
    __nv_bfloat162 lA = {__float2bfloat16(x.x - __bfloat162float(h0)),
                         __float2bfloat16(x.y - __bfloat162float(h1))};
    __nv_bfloat162 lB = {__float2bfloat16(x.z - __bfloat162float(h2)),
                         __float2bfloat16(x.w - __bfloat162float(h3))};
    size_t o = (size_t)z * SEQ * DM + (size_t)i * 4;
    *(uint2*)(g_Xhi + o) = make_uint2(*(uint32_t*)&hA, *(uint32_t*)&hB);
    *(uint2*)(g_Xlo + o) = make_uint2(*(uint32_t*)&lA, *(uint32_t*)&lB);
}

// ---------------------------------------------------------------------------
// conv_w: fp32 weights W[k][n] -> transposed hi/lo bf16 WT[n][k]
// ---------------------------------------------------------------------------
__global__ __launch_bounds__(256) void conv_w(
    const float* __restrict__ LL, const float* __restrict__ bproj)
{
    int z = blockIdx.z;
    const float* W = (z < 3) ? (LL + (size_t)z * DM * DM) : bproj;
    int k0 = blockIdx.y * 32, n0 = blockIdx.x * 32;

    __shared__ float tile[32][33];
    int tid = threadIdx.x;
    #pragma unroll
    for (int i = 0; i < 4; i++) {
        int f = tid + i * 256, r = f >> 5, c = f & 31;
        tile[r][c] = W[(size_t)(k0 + r) * DM + n0 + c];
    }
    __syncthreads();
    #pragma unroll
    for (int i = 0; i < 2; i++) {
        int f = tid + i * 256;          // 0..511
        int r = f >> 4, cp = f & 15;    // r: n row, cp: k pair
        float x0 = tile[2 * cp][r], x1 = tile[2 * cp + 1][r];
        float h0f = __bfloat162float(__float2bfloat16(x0));
        float h1f = __bfloat162float(__float2bfloat16(x1));
        size_t o = (size_t)z * DM * DM + (size_t)(n0 + r) * DM + k0 + 2 * cp;
        *(uint32_t*)(g_Whi + o) = pack_bf16(x0, x1);
        *(uint32_t*)(g_Wlo + o) = pack_bf16(x0 - h0f, x1 - h1f);
    }
}

// ---------------------------------------------------------------------------
// proj_mma: C = X @ W, split-bf16, 3 cross-products.
// BM=128, BN=64, BK=32, 256 thr, 8 warps (4m x 2n), warp tile 32x32.
// cp.async 2-stage ring, 3 CTAs/SM (smem 61.4KB, regs capped <=85).
// ---------------------------------------------------------------------------
#define SAS 40
#define STG 2
#define A_ST (128 * SAS)
#define B_ST (64 * SAS)
#define STAGE_EL (2 * A_ST + 2 * B_ST)
#define PROJ_SMEM (STG * STAGE_EL * 2)

__global__ __launch_bounds__(256, 3) void proj_mma(int zbase)
{
    extern __shared__ __align__(16) __nv_bfloat16 dsm[];

    int z = zbase + blockIdx.z;
    int m0 = blockIdx.y * 128, n0 = blockIdx.x * 64;
    const __nv_bfloat16* Ah = g_Xhi + (size_t)z * SEQ * DM;
    const __nv_bfloat16* Al = g_Xlo + (size_t)z * SEQ * DM;
    const __nv_bfloat16* Bh = g_Whi + (size_t)z * DM * DM;
    const __nv_bfloat16* Bl = g_Wlo + (size_t)z * DM * DM;

    int tid = threadIdx.x, lane = tid & 31, wid = tid >> 5;
    int wm = wid & 3, wn = wid >> 2;

    uint32_t sbase = smem_u32(dsm);

    int ar0 = tid >> 2,         ac0 = tid & 3;
    int ar1 = (tid + 256) >> 2, ac1 = (tid + 256) & 3;
    int br = tid >> 2,          bc = tid & 3;

    const int NCH = DM / 32;

    auto issue = [&](int c) {
        int s = c & 1;
        uint32_t st = sbase + (uint32_t)s * STAGE_EL * 2;
        int k0 = c * 32;
        uint32_t sa0 = st + (uint32_t)(ar0 * SAS + ac0 * 8) * 2;
        uint32_t sa1 = st + (uint32_t)(ar1 * SAS + ac1 * 8) * 2;
        size_t ga0 = (size_t)(m0 + ar0) * DM + k0 + ac0 * 8;
        size_t ga1 = (size_t)(m0 + ar1) * DM + k0 + ac1 * 8;
        CP16(sa0, Ah + ga0);
        CP16(sa0 + A_ST * 2, Al + ga0);
        CP16(sa1, Ah + ga1);
        CP16(sa1 + A_ST * 2, Al + ga1);
        uint32_t sb = st + (uint32_t)(2 * A_ST + br * SAS + bc * 8) * 2;
        size_t gb = (size_t)(n0 + br) * DM + k0 + bc * 8;
        CP16(sb, Bh + gb);
        CP16(sb + B_ST * 2, Bl + gb);
    };

    issue(0); CP_COMMIT();
    issue(1); CP_COMMIT();

    float acc[2][4][4];
    #pragma unroll
    for (int mt = 0; mt < 2; mt++)
        #pragma unroll
        for (int nt = 0; nt < 4; nt++)
            #pragma unroll
            for (int e = 0; e < 4; e++) acc[mt][nt][e] = 0.f;

    int aoff = (wm * 32 + (lane & 15)) * SAS + (lane >> 4) * 8;
    int boff = (wn * 32 + (lane & 7) + ((lane >> 4) & 1) * 8) * SAS
             + ((lane >> 3) & 1) * 8;

    for (int c = 0; c < NCH; c++) {
        CP_WAIT1();
        __syncthreads();     // chunk c landed

        uint32_t st = sbase + (uint32_t)(c & 1) * STAGE_EL * 2;
        uint32_t sa_h = st, sa_l = st + A_ST * 2;
        uint32_t sb_h = st + 2 * A_ST * 2, sb_l = sb_h + B_ST * 2;

        #pragma unroll
        for (int ks = 0; ks < 2; ks++) {
            uint32_t ah[2][4], al[2][4];
            #pragma unroll
            for (int mt = 0; mt < 2; mt++) {
                uint32_t off = (uint32_t)(aoff + mt * 16 * SAS + ks * 16) * 2;
                ldm_x4(ah[mt], sa_h + off);
                ldm_x4(al[mt], sa_l + off);
            }
            uint32_t bh[2][4], bl[2][4];
            #pragma unroll
            for (int np = 0; np < 2; np++) {
                uint32_t off = (uint32_t)(boff + np * 16 * SAS + ks * 16) * 2;
                ldm_x4(bh[np], sb_h + off);
                ldm_x4(bl[np], sb_l + off);
            }
            #pragma unroll
            for (int mt = 0; mt < 2; mt++)
                #pragma unroll
                for (int nt = 0; nt < 4; nt++) {
                    const uint32_t* Bhf = &bh[nt >> 1][(nt & 1) * 2];
                    const uint32_t* Blf = &bl[nt >> 1][(nt & 1) * 2];
                    mma_bf16(acc[mt][nt], ah[mt], Bhf);
                    mma_bf16(acc[mt][nt], ah[mt], Blf);
                    mma_bf16(acc[mt][nt], al[mt], Bhf);
                }
        }
        __syncthreads();     // all warps done with stage c&1
        if (c + 2 < NCH) issue(c + 2);
        CP_COMMIT();         // unconditional: keeps group count
    }

    int mbase = m0 + wm * 32 + (lane >> 2);
    int nbase = n0 + wn * 32 + (lane & 3) * 2;

    if (z == 3) {
        #pragma unroll
        for (int mt = 0; mt < 2; mt++)
            #pragma unroll
            for (int nt = 0; nt < 4; nt++) {
                int mm = mbase + mt * 16, nn = nbase + nt * 8;
                *(float2*)(g_BR + (size_t)mm * DM + nn) =
                    make_float2(acc[mt][nt][0], acc[mt][nt][1]);
                *(float2*)(g_BR + (size_t)(mm + 8) * DM + nn) =
                    make_float2(acc[mt][nt][2], acc[mt][nt][3]);
            }
    } else if (z == 2) {
        #pragma unroll
        for (int mt = 0; mt < 2; mt++)
            #pragma unroll
            for (int nt = 0; nt < 4; nt++) {
                int mm = mbase + mt * 16, nn = nbase + nt * 8;
                #pragma unroll
                for (int half = 0; half < 2; half++) {
                    float x = acc[mt][nt][half * 2], y = acc[mt][nt][half * 2 + 1];
                    float hx = __bfloat162float(__float2bfloat16(x));
                    float hy = __bfloat162float(__float2bfloat16(y));
                    size_t o = (size_t)(mm + half * 8) * DM + nn;
                    *(uint32_t*)(g_Vhi + o) = pack_bf16(x, y);
                    *(uint32_t*)(g_Vlo + o) = pack_bf16(x - hx, y - hy);
                }
            }
    } else {
        __nv_bfloat16* Dhi = (z == 0) ? g_Qhi : g_Khi;
        __nv_bfloat16* Dlo = (z == 0) ? g_Qlo : g_Klo;
        float qscale = (z == 0) ? 0.125f : 1.0f;
        #pragma unroll
        for (int nt = 0; nt < 4; nt++) {
            int nn = nbase + nt * 8;
            int i = (nn & 63) >> 1;
            float inv = (float)exp(-(double)i * (9.210340371976184 / 32.0));
            #pragma unroll
            for (int mt = 0; mt < 2; mt++) {
                #pragma unroll
                for (int half = 0; half < 2; half++) {
                    int mm = mbase + mt * 16 + half * 8;
                    float x1 = acc[mt][nt][half * 2];
                    float x2 = acc[mt][nt][half * 2 + 1];
                    float sa, ca;
                    sincosf((float)mm * inv, &sa, &ca);
                    size_t o = (size_t)mm * DM + nn;
                    float2 br = *(const float2*)(g_BR + o);
                    float e  = (x1 * ca - x2 * sa) * br.x * qscale;
                    float od = (x1 * sa + x2 * ca) * br.y * qscale;
                    float eh = __bfloat162float(__float2bfloat16(e));
                    float oh = __bfloat162float(__float2bfloat16(od));
                    *(uint32_t*)(Dhi + o) = pack_bf16(e, od);
                    *(uint32_t*)(Dlo + o) = pack_bf16(e - eh, od - oh);
                }
            }
        }
    }
}

// ---------------------------------------------------------------------------
// attn_mma: flash attention on mma.sync, cp.async double-buffered K/V,
// one barrier per tile. Grid (SEQ/256, NH), 512 thr / 16 warps.
// ---------------------------------------------------------------------------
#define VS 72
#define KVARR (64 * VS)          // elems per K/V array per stage
#define KVSTAGE (4 * KVARR)      // Kh,Kl,Vh,Vl

__global__ __launch_bounds__(512) void attn_mma(
    const unsigned int* __restrict__ mask, float* __restrict__ out)
{
    extern __shared__ __align__(16) char dyn[];
    __nv_bfloat16* sQh = (__nv_bfloat16*)dyn;            // 256 x VS
    __nv_bfloat16* sQl = sQh + 256 * VS;
    __nv_bfloat16* sKV = sQl + 256 * VS;                 // 2 stages x KVSTAGE
    unsigned char* smk = (unsigned char*)(sKV + 2 * KVSTAGE);

    int h = blockIdx.y, m0 = blockIdx.x * 256;
    int tid = threadIdx.x, lane = tid & 31, wid = tid >> 5;

    for (int i = tid; i < SEQ; i += 512)
        smk[i] = (mask[i] != 0u) ? 1 : 0;

    #pragma unroll
    for (int i = 0; i < 8; i++) {
        int f = tid + i * 512, row = f >> 4, c4 = f & 15;
        size_t g = (size_t)(m0 + row) * DM + h * DK + c4 * 4;
        *(uint2*)(sQh + row * VS + c4 * 4) = *(const uint2*)(g_Qhi + g);
        *(uint2*)(sQl + row * VS + c4 * 4) = *(const uint2*)(g_Qlo + g);
    }

    int r0 = m0 + wid * 16 + (lane >> 2);
    bool mr0 = (mask[r0] != 0u), mr1 = (mask[r0 + 8] != 0u);

    float mx0 = -INFINITY, mx1 = -INFINITY, l0 = 0.f, l1 = 0.f;
    float O[8][4];
    #pragma unroll
    for (int nt = 0; nt < 8; nt++)
        #pragma unroll
        for (int e = 0; e < 4; e++) O[nt][e] = 0.f;

    uint32_t sqh = smem_u32(sQh), sql = smem_u32(sQl);
    uint32_t skv = smem_u32(sKV);

    int qoff = (wid * 16 + (lane & 15)) * VS + (lane >> 4) * 8;
    int kboff = ((lane & 7) + ((lane >> 4) & 1) * 8) * VS + ((lane >> 3) & 1) * 8;
    int voff = (lane & 15) * VS + ((lane >> 4) & 1) * 8;

    int krow = tid >> 3, kc8 = (tid & 7) * 8;
    auto kv_issue = [&](int kb, int buf) {
        uint32_t st = skv + (uint32_t)buf * KVSTAGE * 2;
        size_t g = (size_t)(kb * 64 + krow) * DM + h * DK + kc8;
        uint32_t d = st + (uint32_t)(krow * VS + kc8) * 2;
        CP16(d,                 g_Khi + g);
        CP16(d + KVARR * 2,     g_Klo + g);
        CP16(d + 2 * KVARR * 2, g_Vhi + g);
        CP16(d + 3 * KVARR * 2, g_Vlo + g);
    };

    kv_issue(0, 0); CP_COMMIT();

    for (int kb = 0; kb < SEQ / 64; kb++) {
        CP_WAIT0();
        __syncthreads();

        if (kb + 1 < SEQ / 64) kv_issue(kb + 1, (kb + 1) & 1);
        CP_COMMIT();

        uint32_t st = skv + (uint32_t)(kb & 1) * KVSTAGE * 2;
        uint32_t skh = st, skl = st + KVARR * 2;
        uint32_t svh = st + 2 * KVARR * 2, svl = st + 3 * KVARR * 2;

        float S[8][4];
        #pragma unroll
        for (int nt = 0; nt < 8; nt++)
            #pragma unroll
            for (int e = 0; e < 4; e++) S[nt][e] = 0.f;

        #pragma unroll
        for (int ks = 0; ks < 4; ks++) {
            uint32_t qh[4], ql[4];
            ldm_x4(qh, sqh + (uint32_t)(qoff + ks * 16) * 2);
            ldm_x4(ql, sql + (uint32_t)(qoff + ks * 16) * 2);
            #pragma unroll
            for (int np = 0; np < 4; np++) {
                uint32_t bh[4], bl[4];
                uint32_t off = (uint32_t)(kboff + np * 16 * VS + ks * 16) * 2;
                ldm_x4(bh, skh + off);
                ldm_x4(bl, skl + off);
                mma_bf16(S[2 * np],     qh, &bh[0]);
                mma_bf16(S[2 * np],     qh, &bl[0]);
                mma_bf16(S[2 * np],     ql, &bh[0]);
                mma_bf16(S[2 * np + 1], qh, &bh[2]);
                mma_bf16(S[2 * np + 1], qh, &bl[2]);
                mma_bf16(S[2 * np + 1], ql, &bh[2]);
            }
        }

        float tm0 = -INFINITY, tm1 = -INFINITY;
        #pragma unroll
        for (int nt = 0; nt < 8; nt++) {
            int col = kb * 64 + nt * 8 + (lane & 3) * 2;
            bool c0 = smk[col] != 0, c1 = smk[col + 1] != 0;
            S[nt][0] = (mr0 && c0) ? S[nt][0] : -1e30f;
            S[nt][1] = (mr0 && c1) ? S[nt][1] : -1e30f;
            S[nt][2] = (mr1 && c0) ? S[nt][2] : -1e30f;
            S[nt][3] = (mr1 && c1) ? S[nt][3] : -1e30f;
            tm0 = fmaxf(tm0, fmaxf(S[nt][0], S[nt][1]));
            tm1 = fmaxf(tm1, fmaxf(S[nt][2], S[nt][3]));
        }
        tm0 = fmaxf(tm0, __shfl_xor_sync(0xffffffffu, tm0, 1));
        tm0 = fmaxf(tm0, __shfl_xor_sync(0xffffffffu, tm0, 2));
        tm1 = fmaxf(tm1, __shfl_xor_sync(0xffffffffu, tm1, 1));
        tm1 = fmaxf(tm1, __shfl_xor_sync(0xffffffffu, tm1, 2));

        if (tm0 > mx0) {
            float sc = __expf(mx0 - tm0);
            l0 *= sc;
            #pragma unroll
            for (int nt = 0; nt < 8; nt++) { O[nt][0] *= sc; O[nt][1] *= sc; }
            mx0 = tm0;
        }
        if (tm1 > mx1) {
            float sc = __expf(mx1 - tm1);
            l1 *= sc;
            #pragma unroll
            for (int nt = 0; nt < 8; nt++) { O[nt][2] *= sc; O[nt][3] *= sc; }
            mx1 = tm1;
        }

        uint32_t P0[8], P1[8];
        #pragma unroll
        for (int nt = 0; nt < 8; nt++) {
            float p0 = __expf(S[nt][0] - mx0);
            float p1 = __expf(S[nt][1] - mx0);
            float p2 = __expf(S[nt][2] - mx1);
            float p3 = __expf(S[nt][3] - mx1);
            uint32_t a = pack_bf16(p0, p1);
            uint32_t b = pack_bf16(p2, p3);
            P0[nt] = a; P1[nt] = b;
            l0 += bf2sum(a);
            l1 += bf2sum(b);
        }

        #pragma unroll
        for (int ks2 = 0; ks2 < 4; ks2++) {
            uint32_t af[4] = {P0[2 * ks2], P1[2 * ks2],
                              P0[2 * ks2 + 1], P1[2 * ks2 + 1]};
            #pragma unroll
            for (int np = 0; np < 4; np++) {
                uint32_t vh[4], vl[4];
                uint32_t off = (uint32_t)(voff + ks2 * 16 * VS + np * 16) * 2;
                ldm_x4t(vh, svh + off);
                ldm_x4t(vl, svl + off);
                mma_bf16(O[2 * np],     af, &vh[0]);
                mma_bf16(O[2 * np],     af, &vl[0]);
                mma_bf16(O[2 * np + 1], af, &vh[2]);
                mma_bf16(O[2 * np + 1], af, &vl[2]);
            }
        }
    }

    l0 += __shfl_xor_sync(0xffffffffu, l0, 1);
    l0 += __shfl_xor_sync(0xffffffffu, l0, 2);
    l1 += __shfl_xor_sync(0xffffffffu, l1, 1);
    l1 += __shfl_xor_sync(0xffffffffu, l1, 2);
    float i0 = 1.f / l0, i1 = 1.f / l1;

    #pragma unroll
    for (int nt = 0; nt < 8; nt++) {
        int nn = h * DK + nt * 8 + (lane & 3) * 2;
        *(float2*)(out + (size_t)r0 * DM + nn) =
            make_float2(O[nt][0] * i0, O[nt][1] * i0);
        *(float2*)(out + (size_t)(r0 + 8) * DM + nn) =
            make_float2(O[nt][2] * i1, O[nt][3] * i1);
    }
}

// ---------------------------------------------------------------------------
extern "C" void kernel_launch(void* const* d_in, const int* in_sizes, int n_in,
                              void* d_out, int out_size)
{
    const float* query = (const float*)d_in[0];
    const float* key   = (const float*)d_in[1];
    const float* value = (const float*)d_in[2];
    const float* bemb  = (const float*)d_in[3];
    const unsigned int* mask = (const unsigned int*)d_in[4];
    const float* LL    = (const float*)d_in[5];
    const float* bproj = (const float*)d_in[6];
    float* out = (float*)d_out;

    const int ATTN_SMEM = (2 * 256 * VS + 2 * KVSTAGE) * 2 + SEQ;

    static int smem_set = 0;
    if (!smem_set) {
        cudaFuncSetAttribute(attn_mma,
                             cudaFuncAttributeMaxDynamicSharedMemorySize,
                             ATTN_SMEM);
        cudaFuncSetAttribute(proj_mma,
                             cudaFuncAttributeMaxDynamicSharedMemorySize,
                             PROJ_SMEM);
        smem_set = 1;
    }

    conv_x<<<4 * SEQ * DM / 4 / 256, 256>>>(query, key, value, bemb);
    conv_w<<<dim3(DM / 32, DM / 32, 4), 256>>>(LL, bproj);

    proj_mma<<<dim3(DM / 64, SEQ / 128, 1), 256, PROJ_SMEM>>>(3);  // b_rotate
    proj_mma<<<dim3(DM / 64, SEQ / 128, 3), 256, PROJ_SMEM>>>(0);  // Q,K,V

    attn_mma<<<dim3(SEQ / 256, NH), 512, ATTN_SMEM>>>(mask, out);
}

// round 14
// speedup vs baseline: 1.0633x; 1.0633x over previous
#include <cuda_runtime.h>
#include <cuda_bf16.h>
#include <math.h>
#include <stdint.h>

#define SEQ 2048
#define DM 1024
#define NH 16
#define DK 64

// fp32 intermediate (b_rotate projection)
__device__ float g_BR[SEQ * DM];

// split-bf16 proj inputs [4][SEQ][DM] (q,k,v,b_emb), weights transposed [4][n][k]
__device__ __nv_bfloat16 g_Xhi[4 * SEQ * DM];
__device__ __nv_bfloat16 g_Xlo[4 * SEQ * DM];
__device__ __nv_bfloat16 g_Whi[4 * DM * DM];
__device__ __nv_bfloat16 g_Wlo[4 * DM * DM];
// attention operands (written by proj epilogue, rope fused)
__device__ __nv_bfloat16 g_Qhi[SEQ * DM];
__device__ __nv_bfloat16 g_Qlo[SEQ * DM];
__device__ __nv_bfloat16 g_Khi[SEQ * DM];
__device__ __nv_bfloat16 g_Klo[SEQ * DM];
__device__ __nv_bfloat16 g_Vhi[SEQ * DM];
__device__ __nv_bfloat16 g_Vlo[SEQ * DM];

__device__ __forceinline__ uint32_t smem_u32(const void* p) {
    uint32_t a;
    asm("{ .reg .u64 t; cvta.to.shared.u64 t, %1; cvt.u32.u64 %0, t; }"
        : "=r"(a) : "l"(p));
    return a;
}
__device__ __forceinline__ void ldm_x4(uint32_t r[4], uint32_t addr) {
    asm volatile("ldmatrix.sync.aligned.m8n8.x4.shared.b16 {%0,%1,%2,%3}, [%4];"
                 : "=r"(r[0]), "=r"(r[1]), "=r"(r[2]), "=r"(r[3]) : "r"(addr));
}
__device__ __forceinline__ void ldm_x4t(uint32_t r[4], uint32_t addr) {
    asm volatile("ldmatrix.sync.aligned.m8n8.x4.trans.shared.b16 {%0,%1,%2,%3}, [%4];"
                 : "=r"(r[0]), "=r"(r[1]), "=r"(r[2]), "=r"(r[3]) : "r"(addr));
}
__device__ __forceinline__ void mma_bf16(float c[4], const uint32_t a[4],
                                         const uint32_t* b) {
    asm volatile(
        "mma.sync.aligned.m16n8k16.row.col.f32.bf16.bf16.f32 "
        "{%0,%1,%2,%3}, {%4,%5,%6,%7}, {%8,%9}, {%0,%1,%2,%3};"
        : "+f"(c[0]), "+f"(c[1]), "+f"(c[2]), "+f"(c[3])
        : "r"(a[0]), "r"(a[1]), "r"(a[2]), "r"(a[3]), "r"(b[0]), "r"(b[1]));
}
__device__ __forceinline__ uint32_t pack_bf16(float a, float b) {
    __nv_bfloat162 t = __floats2bfloat162_rn(a, b);
    return *(uint32_t*)&t;
}
__device__ __forceinline__ float bf2sum(uint32_t p) {
    __nv_bfloat162 b = *(__nv_bfloat162*)&p;
    return __bfloat162float(b.x) + __bfloat162float(b.y);
}
#define CP16(s, g) \
    asm volatile("cp.async.cg.shared.global [%0], [%1], 16;" \
                 :: "r"(s), "l"(g) : "memory")
#define CP_COMMIT() asm volatile("cp.async.commit_group;" ::: "memory")
#define CP_WAIT1()  asm volatile("cp.async.wait_group 1;" ::: "memory")
#define CP_WAIT0()  asm volatile("cp.async.wait_group 0;" ::: "memory")

// ---------------------------------------------------------------------------
// conv_x: fp32 inputs -> hi/lo bf16 [4][SEQ][DM]
// ---------------------------------------------------------------------------
__global__ __launch_bounds__(256) void conv_x(
    const float* __restrict__ q, const float* __restrict__ k,
    const float* __restrict__ v, const float* __restrict__ b)
{
    const int PER = SEQ * DM / 4;
    int t = blockIdx.x * 256 + threadIdx.x;
    int z = t / PER, i = t - z * PER;
    const float* src = (z == 0) ? q : (z == 1) ? k : (z == 2) ? v : b;
    float4 x = ((const float4*)src)[i];

    __nv_bfloat16 h0 = __float2bfloat16(x.x), h1 = __float2bfloat16(x.y);
    __nv_bfloat16 h2 = __float2bfloat16(x.z), h3 = __float2bfloat16(x.w);
    __nv_bfloat162 hA = {h0, h1}, hB = {h2, h3};
    __nv_bfloat162 lA = {__float2bfloat16(x.x - __bfloat162float(h0)),
                         __float2bfloat16(x.y - __bfloat162float(h1))};
    __nv_bfloat162 lB = {__float2bfloat16(x.z - __bfloat162float(h2)),
                         __float2bfloat16(x.w - __bfloat162float(h3))};
    size_t o = (size_t)z * SEQ * DM + (size_t)i * 4;
    *(uint2*)(g_Xhi + o) = make_uint2(*(uint32_t*)&hA, *(uint32_t*)&hB);
    *(uint2*)(g_Xlo + o) = make_uint2(*(uint32_t*)&lA, *(uint32_t*)&lB);
}

// ---------------------------------------------------------------------------
// conv_w: fp32 weights W[k][n] -> transposed hi/lo bf16 WT[n][k]
// ---------------------------------------------------------------------------
__global__ __launch_bounds__(256) void conv_w(
    const float* __restrict__ LL, const float* __restrict__ bproj)
{
    int z = blockIdx.z;
    const float* W = (z < 3) ? (LL + (size_t)z * DM * DM) : bproj;
    int k0 = blockIdx.y * 32, n0 = blockIdx.x * 32;

    __shared__ float tile[32][33];
    int tid = threadIdx.x;
    #pragma unroll
    for (int i = 0; i < 4; i++) {
        int f = tid + i * 256, r = f >> 5, c = f & 31;
        tile[r][c] = W[(size_t)(k0 + r) * DM + n0 + c];
    }
    __syncthreads();
    #pragma unroll
    for (int i = 0; i < 2; i++) {
        int f = tid + i * 256;          // 0..511
        int r = f >> 4, cp = f & 15;    // r: n row, cp: k pair
        float x0 = tile[2 * cp][r], x1 = tile[2 * cp + 1][r];
        float h0f = __bfloat162float(__float2bfloat16(x0));
        float h1f = __bfloat162float(__float2bfloat16(x1));
        size_t o = (size_t)z * DM * DM + (size_t)(n0 + r) * DM + k0 + 2 * cp;
        *(uint32_t*)(g_Whi + o) = pack_bf16(x0, x1);
        *(uint32_t*)(g_Wlo + o) = pack_bf16(x0 - h0f, x1 - h1f);
    }
}

// ---------------------------------------------------------------------------
// proj_mma: C = X @ W, split-bf16, 3 cross-products.
// BM=128, BN=64, BK=64 (96 HMMA per warp per barrier episode), 256 thr,
// 8 warps (4m x 2n), warp tile 32x32. cp.async 2-stage ring, 2 CTAs/SM.
// ---------------------------------------------------------------------------
#define SAS2 72
#define STG 2
#define A_ST (128 * SAS2)         // 9216 elems per A array (hi or lo)
#define B_ST (64 * SAS2)          // 4608
#define STAGE_EL (2 * A_ST + 2 * B_ST)   // 27648 elems
#define PROJ_SMEM (STG * STAGE_EL * 2)   // 110592 bytes

__global__ __launch_bounds__(256, 2) void proj_mma(int zbase)
{
    extern __shared__ __align__(16) __nv_bfloat16 dsm[];

    int z = zbase + blockIdx.z;
    int m0 = blockIdx.y * 128, n0 = blockIdx.x * 64;
    const __nv_bfloat16* Ah = g_Xhi + (size_t)z * SEQ * DM;
    const __nv_bfloat16* Al = g_Xlo + (size_t)z * SEQ * DM;
    const __nv_bfloat16* Bh = g_Whi + (size_t)z * DM * DM;
    const __nv_bfloat16* Bl = g_Wlo + (size_t)z * DM * DM;

    int tid = threadIdx.x, lane = tid & 31, wid = tid >> 5;
    int wm = wid & 3, wn = wid >> 2;

    uint32_t sbase = smem_u32(dsm);

    // A: 128 rows x 8 16B-chunks = 1024; thread does 4. B: 64 x 8 = 512; 2.
    int arow[4], ac8[4];
    #pragma unroll
    for (int i = 0; i < 4; i++) { int f = tid + i * 256; arow[i] = f >> 3; ac8[i] = (f & 7) * 8; }
    int brow[2], bc8[2];
    #pragma unroll
    for (int i = 0; i < 2; i++) { int f = tid + i * 256; brow[i] = f >> 3; bc8[i] = (f & 7) * 8; }

    const int NCH = DM / 64;   // 16

    auto issue = [&](int c) {
        uint32_t st = sbase + (uint32_t)(c & 1) * STAGE_EL * 2;
        int k0 = c * 64;
        #pragma unroll
        for (int i = 0; i < 4; i++) {
            uint32_t sa = st + (uint32_t)(arow[i] * SAS2 + ac8[i]) * 2;
            size_t ga = (size_t)(m0 + arow[i]) * DM + k0 + ac8[i];
            CP16(sa, Ah + ga);
            CP16(sa + A_ST * 2, Al + ga);
        }
        #pragma unroll
        for (int i = 0; i < 2; i++) {
            uint32_t sb = st + (uint32_t)(2 * A_ST + brow[i] * SAS2 + bc8[i]) * 2;
            size_t gb = (size_t)(n0 + brow[i]) * DM + k0 + bc8[i];
            CP16(sb, Bh + gb);
            CP16(sb + B_ST * 2, Bl + gb);
        }
    };

    issue(0); CP_COMMIT();
    issue(1); CP_COMMIT();

    float acc[2][4][4];
    #pragma unroll
    for (int mt = 0; mt < 2; mt++)
        #pragma unroll
        for (int nt = 0; nt < 4; nt++)
            #pragma unroll
            for (int e = 0; e < 4; e++) acc[mt][nt][e] = 0.f;

    int aoff = (wm * 32 + (lane & 15)) * SAS2 + (lane >> 4) * 8;
    int boff = (wn * 32 + (lane & 7) + ((lane >> 4) & 1) * 8) * SAS2
             + ((lane >> 3) & 1) * 8;

    for (int c = 0; c < NCH; c++) {
        CP_WAIT1();
        __syncthreads();     // chunk c landed

        uint32_t st = sbase + (uint32_t)(c & 1) * STAGE_EL * 2;
        uint32_t sa_h = st, sa_l = st + A_ST * 2;
        uint32_t sb_h = st + 2 * A_ST * 2, sb_l = sb_h + B_ST * 2;

        #pragma unroll
        for (int ks = 0; ks < 4; ks++) {
            uint32_t ah[2][4], al[2][4];
            #pragma unroll
            for (int mt = 0; mt < 2; mt++) {
                uint32_t off = (uint32_t)(aoff + mt * 16 * SAS2 + ks * 16) * 2;
                ldm_x4(ah[mt], sa_h + off);
                ldm_x4(al[mt], sa_l + off);
            }
            uint32_t bh[2][4], bl[2][4];
            #pragma unroll
            for (int np = 0; np < 2; np++) {
                uint32_t off = (uint32_t)(boff + np * 16 * SAS2 + ks * 16) * 2;
                ldm_x4(bh[np], sb_h + off);
                ldm_x4(bl[np], sb_l + off);
            }
            #pragma unroll
            for (int mt = 0; mt < 2; mt++)
                #pragma unroll
                for (int nt = 0; nt < 4; nt++) {
                    const uint32_t* Bhf = &bh[nt >> 1][(nt & 1) * 2];
                    const uint32_t* Blf = &bl[nt >> 1][(nt & 1) * 2];
                    mma_bf16(acc[mt][nt], ah[mt], Bhf);
                    mma_bf16(acc[mt][nt], ah[mt], Blf);
                    mma_bf16(acc[mt][nt], al[mt], Bhf);
                }
        }
        __syncthreads();     // all warps done with stage c&1
        if (c + 2 < NCH) issue(c + 2);
        CP_COMMIT();         // unconditional: keeps group count
    }

    int mbase = m0 + wm * 32 + (lane >> 2);
    int nbase = n0 + wn * 32 + (lane & 3) * 2;

    if (z == 3) {
        #pragma unroll
        for (int mt = 0; mt < 2; mt++)
            #pragma unroll
            for (int nt = 0; nt < 4; nt++) {
                int mm = mbase + mt * 16, nn = nbase + nt * 8;
                *(float2*)(g_BR + (size_t)mm * DM + nn) =
                    make_float2(acc[mt][nt][0], acc[mt][nt][1]);
                *(float2*)(g_BR + (size_t)(mm + 8) * DM + nn) =
                    make_float2(acc[mt][nt][2], acc[mt][nt][3]);
            }
    } else if (z == 2) {
        #pragma unroll
        for (int mt = 0; mt < 2; mt++)
            #pragma unroll
            for (int nt = 0; nt < 4; nt++) {
                int mm = mbase + mt * 16, nn = nbase + nt * 8;
                #pragma unroll
                for (int half = 0; half < 2; half++) {
                    float x = acc[mt][nt][half * 2], y = acc[mt][nt][half * 2 + 1];
                    float hx = __bfloat162float(__float2bfloat16(x));
                    float hy = __bfloat162float(__float2bfloat16(y));
                    size_t o = (size_t)(mm + half * 8) * DM + nn;
                    *(uint32_t*)(g_Vhi + o) = pack_bf16(x, y);
                    *(uint32_t*)(g_Vlo + o) = pack_bf16(x - hx, y - hy);
                }
            }
    } else {
        __nv_bfloat16* Dhi = (z == 0) ? g_Qhi : g_Khi;
        __nv_bfloat16* Dlo = (z == 0) ? g_Qlo : g_Klo;
        float qscale = (z == 0) ? 0.125f : 1.0f;
        #pragma unroll
        for (int nt = 0; nt < 4; nt++) {
            int nn = nbase + nt * 8;
            int i = (nn & 63) >> 1;
            float inv = (float)exp(-(double)i * (9.210340371976184 / 32.0));
            #pragma unroll
            for (int mt = 0; mt < 2; mt++) {
                #pragma unroll
                for (int half = 0; half < 2; half++) {
                    int mm = mbase + mt * 16 + half * 8;
                    float x1 = acc[mt][nt][half * 2];
                    float x2 = acc[mt][nt][half * 2 + 1];
                    float sa, ca;
                    sincosf((float)mm * inv, &sa, &ca);
                    size_t o = (size_t)mm * DM + nn;
                    float2 br = *(const float2*)(g_BR + o);
                    float e  = (x1 * ca - x2 * sa) * br.x * qscale;
                    float od = (x1 * sa + x2 * ca) * br.y * qscale;
                    float eh = __bfloat162float(__float2bfloat16(e));
                    float oh = __bfloat162float(__float2bfloat16(od));
                    *(uint32_t*)(Dhi + o) = pack_bf16(e, od);
                    *(uint32_t*)(Dlo + o) = pack_bf16(e - eh, od - oh);
                }
            }
        }
    }
}

// ---------------------------------------------------------------------------
// attn_mma: flash attention on mma.sync, cp.async double-buffered K/V,
// one barrier per tile. Grid (SEQ/256, NH), 512 thr / 16 warps.
// ---------------------------------------------------------------------------
#define VS 72
#define KVARR (64 * VS)          // elems per K/V array per stage
#define KVSTAGE (4 * KVARR)      // Kh,Kl,Vh,Vl

__global__ __launch_bounds__(512) void attn_mma(
    const unsigned int* __restrict__ mask, float* __restrict__ out)
{
    extern __shared__ __align__(16) char dyn[];
    __nv_bfloat16* sQh = (__nv_bfloat16*)dyn;            // 256 x VS
    __nv_bfloat16* sQl = sQh + 256 * VS;
    __nv_bfloat16* sKV = sQl + 256 * VS;                 // 2 stages x KVSTAGE
    unsigned char* smk = (unsigned char*)(sKV + 2 * KVSTAGE);

    int h = blockIdx.y, m0 = blockIdx.x * 256;
    int tid = threadIdx.x, lane = tid & 31, wid = tid >> 5;

    for (int i = tid; i < SEQ; i += 512)
        smk[i] = (mask[i] != 0u) ? 1 : 0;

    #pragma unroll
    for (int i = 0; i < 8; i++) {
        int f = tid + i * 512, row = f >> 4, c4 = f & 15;
        size_t g = (size_t)(m0 + row) * DM + h * DK + c4 * 4;
        *(uint2*)(sQh + row * VS + c4 * 4) = *(const uint2*)(g_Qhi + g);
        *(uint2*)(sQl + row * VS + c4 * 4) = *(const uint2*)(g_Qlo + g);
    }

    int r0 = m0 + wid * 16 + (lane >> 2);
    bool mr0 = (mask[r0] != 0u), mr1 = (mask[r0 + 8] != 0u);

    float mx0 = -INFINITY, mx1 = -INFINITY, l0 = 0.f, l1 = 0.f;
    float O[8][4];
    #pragma unroll
    for (int nt = 0; nt < 8; nt++)
        #pragma unroll
        for (int e = 0; e < 4; e++) O[nt][e] = 0.f;

    uint32_t sqh = smem_u32(sQh), sql = smem_u32(sQl);
    uint32_t skv = smem_u32(sKV);

    int qoff = (wid * 16 + (lane & 15)) * VS + (lane >> 4) * 8;
    int kboff = ((lane & 7) + ((lane >> 4) & 1) * 8) * VS + ((lane >> 3) & 1) * 8;
    int voff = (lane & 15) * VS + ((lane >> 4) & 1) * 8;

    int krow = tid >> 3, kc8 = (tid & 7) * 8;
    auto kv_issue = [&](int kb, int buf) {
        uint32_t st = skv + (uint32_t)buf * KVSTAGE * 2;
        size_t g = (size_t)(kb * 64 + krow) * DM + h * DK + kc8;
        uint32_t d = st + (uint32_t)(krow * VS + kc8) * 2;
        CP16(d,                 g_Khi + g);
        CP16(d + KVARR * 2,     g_Klo + g);
        CP16(d + 2 * KVARR * 2, g_Vhi + g);
        CP16(d + 3 * KVARR * 2, g_Vlo + g);
    };

    kv_issue(0, 0); CP_COMMIT();

    for (int kb = 0; kb < SEQ / 64; kb++) {
        CP_WAIT0();
        __syncthreads();

        if (kb + 1 < SEQ / 64) kv_issue(kb + 1, (kb + 1) & 1);
        CP_COMMIT();

        uint32_t st = skv + (uint32_t)(kb & 1) * KVSTAGE * 2;
        uint32_t skh = st, skl = st + KVARR * 2;
        uint32_t svh = st + 2 * KVARR * 2, svl = st + 3 * KVARR * 2;

        float S[8][4];
        #pragma unroll
        for (int nt = 0; nt < 8; nt++)
            #pragma unroll
            for (int e = 0; e < 4; e++) S[nt][e] = 0.f;

        #pragma unroll
        for (int ks = 0; ks < 4; ks++) {
            uint32_t qh[4], ql[4];
            ldm_x4(qh, sqh + (uint32_t)(qoff + ks * 16) * 2);
            ldm_x4(ql, sql + (uint32_t)(qoff + ks * 16) * 2);
            #pragma unroll
            for (int np = 0; np < 4; np++) {
                uint32_t bh[4], bl[4];
                uint32_t off = (uint32_t)(kboff + np * 16 * VS + ks * 16) * 2;
                ldm_x4(bh, skh + off);
                ldm_x4(bl, skl + off);
                mma_bf16(S[2 * np],     qh, &bh[0]);
                mma_bf16(S[2 * np],     qh, &bl[0]);
                mma_bf16(S[2 * np],     ql, &bh[0]);
                mma_bf16(S[2 * np + 1], qh, &bh[2]);
                mma_bf16(S[2 * np + 1], qh, &bl[2]);
                mma_bf16(S[2 * np + 1], ql, &bh[2]);
            }
        }

        float tm0 = -INFINITY, tm1 = -INFINITY;
        #pragma unroll
        for (int nt = 0; nt < 8; nt++) {
            int col = kb * 64 + nt * 8 + (lane & 3) * 2;
            bool c0 = smk[col] != 0, c1 = smk[col + 1] != 0;
            S[nt][0] = (mr0 && c0) ? S[nt][0] : -1e30f;
            S[nt][1] = (mr0 && c1) ? S[nt][1] : -1e30f;
            S[nt][2] = (mr1 && c0) ? S[nt][2] : -1e30f;
            S[nt][3] = (mr1 && c1) ? S[nt][3] : -1e30f;
            tm0 = fmaxf(tm0, fmaxf(S[nt][0], S[nt][1]));
            tm1 = fmaxf(tm1, fmaxf(S[nt][2], S[nt][3]));
        }
        tm0 = fmaxf(tm0, __shfl_xor_sync(0xffffffffu, tm0, 1));
        tm0 = fmaxf(tm0, __shfl_xor_sync(0xffffffffu, tm0, 2));
        tm1 = fmaxf(tm1, __shfl_xor_sync(0xffffffffu, tm1, 1));
        tm1 = fmaxf(tm1, __shfl_xor_sync(0xffffffffu, tm1, 2));

        if (tm0 > mx0) {
            float sc = __expf(mx0 - tm0);
            l0 *= sc;
            #pragma unroll
            for (int nt = 0; nt < 8; nt++) { O[nt][0] *= sc; O[nt][1] *= sc; }
            mx0 = tm0;
        }
        if (tm1 > mx1) {
            float sc = __expf(mx1 - tm1);
            l1 *= sc;
            #pragma unroll
            for (int nt = 0; nt < 8; nt++) { O[nt][2] *= sc; O[nt][3] *= sc; }
            mx1 = tm1;
        }

        uint32_t P0[8], P1[8];
        #pragma unroll
        for (int nt = 0; nt < 8; nt++) {
            float p0 = __expf(S[nt][0] - mx0);
            float p1 = __expf(S[nt][1] - mx0);
            float p2 = __expf(S[nt][2] - mx1);
            float p3 = __expf(S[nt][3] - mx1);
            uint32_t a = pack_bf16(p0, p1);
            uint32_t b = pack_bf16(p2, p3);
            P0[nt] = a; P1[nt] = b;
            l0 += bf2sum(a);
            l1 += bf2sum(b);
        }

        #pragma unroll
        for (int ks2 = 0; ks2 < 4; ks2++) {
            uint32_t af[4] = {P0[2 * ks2], P1[2 * ks2],
                              P0[2 * ks2 + 1], P1[2 * ks2 + 1]};
            #pragma unroll
            for (int np = 0; np < 4; np++) {
                uint32_t vh[4], vl[4];
                uint32_t off = (uint32_t)(voff + ks2 * 16 * VS + np * 16) * 2;
                ldm_x4t(vh, svh + off);
                ldm_x4t(vl, svl + off);
                mma_bf16(O[2 * np],     af, &vh[0]);
                mma_bf16(O[2 * np],     af, &vl[0]);
                mma_bf16(O[2 * np + 1], af, &vh[2]);
                mma_bf16(O[2 * np + 1], af, &vl[2]);
            }
        }
    }

    l0 += __shfl_xor_sync(0xffffffffu, l0, 1);
    l0 += __shfl_xor_sync(0xffffffffu, l0, 2);
    l1 += __shfl_xor_sync(0xffffffffu, l1, 1);
    l1 += __shfl_xor_sync(0xffffffffu, l1, 2);
    float i0 = 1.f / l0, i1 = 1.f / l1;

    #pragma unroll
    for (int nt = 0; nt < 8; nt++) {
        int nn = h * DK + nt * 8 + (lane & 3) * 2;
        *(float2*)(out + (size_t)r0 * DM + nn) =
            make_float2(O[nt][0] * i0, O[nt][1] * i0);
        *(float2*)(out + (size_t)(r0 + 8) * DM + nn) =
            make_float2(O[nt][2] * i1, O[nt][3] * i1);
    }
}

// ---------------------------------------------------------------------------
extern "C" void kernel_launch(void* const* d_in, const int* in_sizes, int n_in,
                              void* d_out, int out_size)
{
    const float* query = (const float*)d_in[0];
    const float* key   = (const float*)d_in[1];
    const float* value = (const float*)d_in[2];
    const float* bemb  = (const float*)d_in[3];
    const unsigned int* mask = (const unsigned int*)d_in[4];
    const float* LL    = (const float*)d_in[5];
    const float* bproj = (const float*)d_in[6];
    float* out = (float*)d_out;

    const int ATTN_SMEM = (2 * 256 * VS + 2 * KVSTAGE) * 2 + SEQ;

    static int smem_set = 0;
    if (!smem_set) {
        cudaFuncSetAttribute(attn_mma,
                             cudaFuncAttributeMaxDynamicSharedMemorySize,
                             ATTN_SMEM);
        cudaFuncSetAttribute(proj_mma,
                             cudaFuncAttributeMaxDynamicSharedMemorySize,
                             PROJ_SMEM);
        smem_set = 1;
    }

    conv_x<<<4 * SEQ * DM / 4 / 256, 256>>>(query, key, value, bemb);
    conv_w<<<dim3(DM / 32, DM / 32, 4), 256>>>(LL, bproj);

    proj_mma<<<dim3(DM / 64, SEQ / 128, 1), 256, PROJ_SMEM>>>(3);  // b_rotate
    proj_mma<<<dim3(DM / 64, SEQ / 128, 3), 256, PROJ_SMEM>>>(0);  // Q,K,V

    attn_mma<<<dim3(SEQ / 256, NH), 512, ATTN_SMEM>>>(mask, out);
}